// round 9
// baseline (speedup 1.0000x reference)
#include <cuda_runtime.h>
#include <math.h>
#include <stdint.h>

#define B_  2
#define T_  2048
#define D_  1024
#define H_  16
#define DH_ 64
#define NTOK (B_*T_)          // 4096
#define K3  3072
#define NCH 16                // EMA chunks
#define CHL (T_/NCH)          // 128

// ---------------- scratch (device globals; no allocation) ----------------
__device__ __align__(256) float g_integral[(size_t)NTOK * D_];
__device__ float g_params[(size_t)NTOK * 12];
__device__ float g_ends[(size_t)NCH * B_ * D_];
__device__ float g_carry[(size_t)NCH * B_ * D_];
// int8 dual-level quantized operands
__device__ __align__(256) int8_t g_a1[(size_t)3 * NTOK * K3];
__device__ __align__(256) int8_t g_a2[(size_t)3 * NTOK * K3];
__device__ __align__(256) int8_t g_w1[(size_t)3 * 1024 * K3];
__device__ __align__(256) int8_t g_w2[(size_t)3 * 1024 * K3];
__device__ __align__(256) int8_t g_o1[(size_t)NTOK * D_];
__device__ __align__(256) int8_t g_o2[(size_t)NTOK * D_];
__device__ __align__(256) int8_t g_ow1[(size_t)1024 * 1024];
__device__ __align__(256) int8_t g_ow2[(size_t)1024 * 1024];
// per-row scales
__device__ float g_sa[(size_t)3 * NTOK];
__device__ float g_sw[(size_t)3 * 1024];
__device__ float g_so[(size_t)NTOK];
__device__ float g_sow[(size_t)1024];
// fp32 intermediates
__device__ __align__(256) float g_q[(size_t)NTOK * D_];
__device__ __align__(256) float g_k[(size_t)NTOK * D_];
__device__ __align__(256) float g_v[(size_t)NTOK * D_];
__device__ __align__(256) float g_att[(size_t)NTOK * D_];

// ============================ PTX helpers (sm_100-baseline safe) ============================
__device__ __forceinline__ uint32_t s2u(const void* p) {
    uint32_t a;
    asm("{ .reg .u64 t; cvta.to.shared.u64 t, %1; cvt.u32.u64 %0, t; }" : "=r"(a) : "l"(p));
    return a;
}
__device__ __forceinline__ void cp_async16(uint32_t dst, const void* src) {
    asm volatile("cp.async.cg.shared.global [%0], [%1], 16;" :: "r"(dst), "l"(src));
}
__device__ __forceinline__ void cp_commit() {
    asm volatile("cp.async.commit_group;" ::: "memory");
}
__device__ __forceinline__ void cp_wait1() {
    asm volatile("cp.async.wait_group 1;" ::: "memory");
}
__device__ __forceinline__ void ldsm_x4(uint32_t* r, uint32_t addr) {
    asm volatile("ldmatrix.sync.aligned.m8n8.x4.shared.b16 {%0,%1,%2,%3}, [%4];"
        : "=r"(r[0]), "=r"(r[1]), "=r"(r[2]), "=r"(r[3]) : "r"(addr));
}
__device__ __forceinline__ void mma_s8(int* d, const uint32_t* a, const uint32_t* b) {
    asm volatile(
        "mma.sync.aligned.m16n8k32.row.col.s32.s8.s8.s32 "
        "{%0,%1,%2,%3}, {%4,%5,%6,%7}, {%8,%9}, {%0,%1,%2,%3};"
        : "+r"(d[0]), "+r"(d[1]), "+r"(d[2]), "+r"(d[3])
        : "r"(a[0]), "r"(a[1]), "r"(a[2]), "r"(a[3]), "r"(b[0]), "r"(b[1]));
}

// ============================ misc kernels ============================
__global__ void token_stats_kernel(const float* __restrict__ x,
                                   const float* __restrict__ gate_w,
                                   const float* __restrict__ gate_b,
                                   const float* __restrict__ kick_w,
                                   const float* __restrict__ kick_b)
{
    int r = blockIdx.x;
    int t = r % T_;
    const float* xt = x + (size_t)r * D_;
    int tid = threadIdx.x;

    float acc[15];
#pragma unroll
    for (int v = 0; v < 15; v++) acc[v] = 0.f;

    for (int d = tid; d < D_; d += 128) {
        float xv = xt[d];
        float pv = (t > 0) ? xt[d - D_] : 0.f;
        acc[0] = fmaf(xv, xv, acc[0]);
        acc[1] = fmaf(xv, pv, acc[1]);
        acc[2] = fmaf(pv, pv, acc[2]);
        acc[3] = fmaf(xv, kick_w[0 * D_ + d], acc[3]);
        acc[4] = fmaf(xv, kick_w[1 * D_ + d], acc[4]);
        acc[5] = fmaf(xv, kick_w[2 * D_ + d], acc[5]);
#pragma unroll
        for (int j = 0; j < 9; j++)
            acc[6 + j] = fmaf(xv, gate_w[j * D_ + d], acc[6 + j]);
    }
#pragma unroll
    for (int v = 0; v < 15; v++)
#pragma unroll
        for (int off = 16; off; off >>= 1)
            acc[v] += __shfl_down_sync(0xffffffffu, acc[v], off);

    __shared__ float red[15][4];
    int w = tid >> 5, l = tid & 31;
    if (l == 0)
#pragma unroll
        for (int v = 0; v < 15; v++) red[v][w] = acc[v];
    __syncthreads();

    if (tid == 0) {
        float s[15];
#pragma unroll
        for (int v = 0; v < 15; v++)
            s[v] = red[v][0] + red[v][1] + red[v][2] + red[v][3];
        float nt = fmaxf(sqrtf(s[0]), 1e-12f);
        float np = fmaxf(sqrtf(s[2]), 1e-12f);
        float cosv = (t > 0) ? s[1] / (nt * np) : 0.f;
        float stag = (cosv > 0.95f) ? 1.f : 0.f;
        float* out = g_params + (size_t)r * 12;
#pragma unroll
        for (int p = 0; p < 3; p++) {
            float ks = 1.f / (1.f + expf(-(s[3 + p] + kick_b[p])));
            float l0 = s[6 + p * 3 + 0] + gate_b[p * 3 + 0];
            float l1 = s[6 + p * 3 + 1] + gate_b[p * 3 + 1];
            float l2 = s[6 + p * 3 + 2] + gate_b[p * 3 + 2];
            float m = fmaxf(l0, fmaxf(l1, l2));
            float e0 = expf(l0 - m), e1 = expf(l1 - m), e2 = expf(l2 - m);
            float inv = 1.f / (e0 + e1 + e2);
            float g0 = fminf(e0 * inv, 0.6f);
            float g1 = fminf(e1 * inv, 0.6f);
            float g2 = fminf(e2 * inv, 0.6f);
            g1 = fmaxf(g1, 0.25f);
            float gi = 1.f / (g0 + g1 + g2);
            out[p * 4 + 0] = g0 * gi;
            out[p * 4 + 1] = g1 * gi;
            out[p * 4 + 2] = g2 * gi;
            out[p * 4 + 3] = stag * ks;
        }
    }
}

// ---------------- EMA: 3-pass chunked scan ----------------
// pass 1: local EMA per (channel, chunk), zero-carry; record chunk-end value
__global__ void ema_pass1(const float* __restrict__ x)
{
    int id = blockIdx.x * blockDim.x + threadIdx.x;
    if (id >= NCH * B_ * D_) return;
    int ch = id & (B_ * D_ - 1);       // 2048 channels
    int c = id >> 11;
    int b = ch >> 10, d = ch & 1023;
    const float* xp = x + (size_t)b * T_ * D_ + d;
    float* ip = g_integral + (size_t)b * T_ * D_ + d;
    int t0 = c * CHL;
    float acc;
    int ts;
    if (c == 0) {
        acc = xp[0];
        ip[0] = acc;
        ts = 1;
    } else {
        acc = 0.f;
        ts = t0;
    }
#pragma unroll 8
    for (int t = ts; t < t0 + CHL; t++) {
        acc = fmaf(0.95f, acc, 0.05f * xp[(size_t)t * D_]);
        ip[(size_t)t * D_] = acc;
    }
    g_ends[(size_t)c * (B_ * D_) + ch] = acc;
}

// pass 2: serial carry across 16 chunks per channel
__global__ void ema_pass2()
{
    int ch = blockIdx.x * blockDim.x + threadIdx.x;
    if (ch >= B_ * D_) return;
    float dL = __powf(0.95f, (float)CHL);
    float carry = 0.f;
    g_carry[ch] = 0.f;
    for (int c = 1; c < NCH; c++) {
        carry = fmaf(dL, carry, g_ends[(size_t)(c - 1) * (B_ * D_) + ch]);
        g_carry[(size_t)c * (B_ * D_) + ch] = carry;
    }
}

// pass 3: fixup chunks 1..15: y[t] = local[t] + 0.95^{off+1} * carry
__global__ void ema_pass3()
{
    int id = blockIdx.x * blockDim.x + threadIdx.x;
    if (id >= (NCH - 1) * B_ * D_) return;
    int ch = id & (B_ * D_ - 1);
    int c = 1 + (id >> 11);
    int b = ch >> 10, d = ch & 1023;
    float f = g_carry[(size_t)c * (B_ * D_) + ch];
    if (f == 0.f) return;
    float* ip = g_integral + (size_t)b * T_ * D_ + d;
    int t0 = c * CHL;
#pragma unroll 8
    for (int t = t0; t < t0 + CHL; t++) {
        f *= 0.95f;
        ip[(size_t)t * D_] += f;
    }
}

// ---------------- quantization helpers ----------------
__device__ __forceinline__ float block_max256(float mx) {
    __shared__ float red[8];
#pragma unroll
    for (int o = 16; o; o >>= 1)
        mx = fmaxf(mx, __shfl_xor_sync(0xffffffffu, mx, o));
    int w = threadIdx.x >> 5;
    if ((threadIdx.x & 31) == 0) red[w] = mx;
    __syncthreads();
    float m = fmaxf(fmaxf(red[0], red[1]), fmaxf(red[2], red[3]));
    m = fmaxf(m, fmaxf(fmaxf(red[4], red[5]), fmaxf(red[6], red[7])));
    return m;
}

__device__ __forceinline__ void quant2(float t, int8_t& q1, int8_t& q2) {
    int a1 = __float2int_rn(t);
    int a2 = __float2int_rn((t - (float)a1) * 256.f);
    a2 = max(-127, min(127, a2));
    q1 = (int8_t)a1;
    q2 = (int8_t)a2;
}

__device__ __forceinline__ void quant_store4(int8_t* d1, int8_t* d2, size_t idx,
                                             const float* v, float inv) {
    char4 c1, c2;
    quant2(v[0] * inv, (int8_t&)c1.x, (int8_t&)c2.x);
    quant2(v[1] * inv, (int8_t&)c1.y, (int8_t&)c2.y);
    quant2(v[2] * inv, (int8_t&)c1.z, (int8_t&)c2.z);
    quant2(v[3] * inv, (int8_t&)c1.w, (int8_t&)c2.w);
    *(char4*)(d1 + idx) = c1;
    *(char4*)(d2 + idx) = c2;
}

__global__ void build_abc_q(const float* __restrict__ x,
                            const float* __restrict__ kick_v)
{
    int r = blockIdx.x;
    int p = blockIdx.y;
    int t = r % T_;
    const float* par = g_params + (size_t)r * 12 + p * 4;
    float g0 = par[0], g1 = par[1], g2 = par[2], km = par[3];
    const float* xt = x + (size_t)r * D_;
    const float* integ = g_integral + (size_t)r * D_;
    int d = threadIdx.x * 4;

    float v[12];
    float4 xv = *(const float4*)(xt + d);
    float4 iv = *(const float4*)(integ + d);
    float4 kv = *(const float4*)(kick_v + p * D_ + d);
    float4 pv = (t > 0) ? *(const float4*)(xt + d - D_)
                        : make_float4(xv.x, xv.y, xv.z, xv.w);
    v[0] = g0 * xv.x; v[1] = g0 * xv.y; v[2] = g0 * xv.z; v[3] = g0 * xv.w;
    v[4] = g1 * iv.x; v[5] = g1 * iv.y; v[6] = g1 * iv.z; v[7] = g1 * iv.w;
    v[8]  = g2 * fmaf(km, kv.x, xv.x - pv.x);
    v[9]  = g2 * fmaf(km, kv.y, xv.y - pv.y);
    v[10] = g2 * fmaf(km, kv.z, xv.z - pv.z);
    v[11] = g2 * fmaf(km, kv.w, xv.w - pv.w);

    float mx = 0.f;
#pragma unroll
    for (int j = 0; j < 12; j++) mx = fmaxf(mx, fabsf(v[j]));
    mx = block_max256(mx);
    float inv = (mx > 0.f) ? 127.f / mx : 0.f;

    size_t base = ((size_t)p * NTOK + r) * K3;
    quant_store4(g_a1, g_a2, base + d,            v,     inv);
    quant_store4(g_a1, g_a2, base + D_ + d,       v + 4, inv);
    quant_store4(g_a1, g_a2, base + 2 * D_ + d,   v + 8, inv);
    if (threadIdx.x == 0) g_sa[(size_t)p * NTOK + r] = mx * (1.f / 127.f);
}

__global__ void conv_w_q(const float* __restrict__ Wp,
                         const float* __restrict__ Wi,
                         const float* __restrict__ Wd)
{
    int n = blockIdx.x;
    int p = blockIdx.y;
    int d = threadIdx.x * 4;
    size_t roff = ((size_t)p * 1024 + n) * 1024 + d;
    float v[12];
    *(float4*)(v)     = *(const float4*)(Wp + roff);
    *(float4*)(v + 4) = *(const float4*)(Wi + roff);
    *(float4*)(v + 8) = *(const float4*)(Wd + roff);

    float mx = 0.f;
#pragma unroll
    for (int j = 0; j < 12; j++) mx = fmaxf(mx, fabsf(v[j]));
    mx = block_max256(mx);
    float inv = (mx > 0.f) ? 127.f / mx : 0.f;

    size_t base = ((size_t)p * 1024 + n) * K3;
    quant_store4(g_w1, g_w2, base + d,            v,     inv);
    quant_store4(g_w1, g_w2, base + 1024 + d,     v + 4, inv);
    quant_store4(g_w1, g_w2, base + 2048 + d,     v + 8, inv);
    if (threadIdx.x == 0) g_sw[(size_t)p * 1024 + n] = mx * (1.f / 127.f);
}

__global__ void quant_rows_q(const float* __restrict__ src,
                             int8_t* __restrict__ d1, int8_t* __restrict__ d2,
                             float* __restrict__ sc)
{
    int r = blockIdx.x;
    int d = threadIdx.x * 4;
    float v[4];
    *(float4*)v = *(const float4*)(src + (size_t)r * 1024 + d);
    float mx = fmaxf(fmaxf(fabsf(v[0]), fabsf(v[1])), fmaxf(fabsf(v[2]), fabsf(v[3])));
    mx = block_max256(mx);
    float inv = (mx > 0.f) ? 127.f / mx : 0.f;
    quant_store4(d1, d2, (size_t)r * 1024 + d, v, inv);
    if (threadIdx.x == 0) sc[r] = mx * (1.f / 127.f);
}

// ============================ int8 dual-level mma GEMM v2 ============================
// 2 CTAs/SM: CTA tile 128(M) x 64(N), 4 warps 2x2 (warp tile 64x32), KT=64 int8,
// 3-stage cp.async. C = sA*sB*(A1*B1 + (A1*B2 + A2*B1)/256), exact int32 accum.
#define GSTG    3
#define KTQ     64
#define ROWB    80                     // 64B data + 16B skew (80/16=5 coprime w/ 8 -> conflict-free)
#define A1T     (128 * ROWB)           // 10240
#define B1T     (64 * ROWB)            // 5120
#define OFF_A2  A1T
#define OFF_B1  (2 * A1T)
#define OFF_B2  (2 * A1T + B1T)
#define STAGE_SZ (2 * A1T + 2 * B1T)   // 30720
#define GEMM_SMEM (GSTG * STAGE_SZ)    // 92160 per CTA; 2 CTAs = 184320/SM

__device__ __forceinline__ void issue_s8(
    const int8_t* A1, const int8_t* A2, const int8_t* B1, const int8_t* B2,
    int K, uint32_t su, int tid, int stage, int koff, int m0, int brow0)
{
    uint32_t st = su + stage * STAGE_SZ;
    // 1536 16B-chunks: a1[0,512) a2[512,1024) b1[1024,1280) b2[1280,1536)
#pragma unroll
    for (int j = 0; j < 12; j++) {
        int i = tid + j * 128;
        const int8_t* srcb;
        uint32_t toff;
        int idx;
        if (i < 512)        { srcb = A1; toff = 0;      idx = i; }
        else if (i < 1024)  { srcb = A2; toff = OFF_A2; idx = i - 512; }
        else if (i < 1280)  { srcb = B1; toff = OFF_B1; idx = i - 1024; }
        else                { srcb = B2; toff = OFF_B2; idx = i - 1280; }
        int row = idx >> 2, c = idx & 3;
        int rbase = (i < 1024) ? m0 : brow0;
        cp_async16(st + toff + row * ROWB + c * 16,
                   srcb + (size_t)(rbase + row) * K + koff + c * 16);
    }
    cp_commit();
}

__global__ void __launch_bounds__(128, 2)
gemm_s8(const int8_t* __restrict__ A1, const int8_t* __restrict__ A2,
        const int8_t* __restrict__ B1, const int8_t* __restrict__ B2,
        const float* __restrict__ sa, const float* __restrict__ sbv,
        float* c0, float* c1, float* c2, int nchunks, int K)
{
    extern __shared__ __align__(256) char smem[];
    uint32_t su = s2u(smem);
    int tid = threadIdx.x, lane = tid & 31, wid = tid >> 5;
    int wm = wid >> 1, wn = wid & 1;       // 2 x 2, warp tile 64x32
    int by = blockIdx.y, bx = blockIdx.x;
    int proj = by >> 5;
    int m0 = by * 128;
    int brow0 = proj * 1024 + bx * 64;

    int hi[4][4][4], mi[4][4][4];
#pragma unroll
    for (int i = 0; i < 4; i++)
#pragma unroll
        for (int j = 0; j < 4; j++)
#pragma unroll
            for (int q = 0; q < 4; q++) { hi[i][j][q] = 0; mi[i][j][q] = 0; }

    uint32_t a_off = (uint32_t)((wm * 64 + (lane & 15)) * ROWB + (lane >> 4) * 16);
    uint32_t b_off = (uint32_t)(OFF_B1
                     + (wn * 32 + ((lane >> 4) << 3) + (lane & 7)) * ROWB
                     + ((lane >> 3) & 1) * 16);

    issue_s8(A1, A2, B1, B2, K, su, tid, 0, 0, m0, brow0);
    issue_s8(A1, A2, B1, B2, K, su, tid, 1, KTQ, m0, brow0);

    for (int kc = 0; kc < nchunks; kc++) {
        cp_wait1();
        __syncthreads();
        if (kc + 2 < nchunks)
            issue_s8(A1, A2, B1, B2, K, su, tid, (kc + 2) % GSTG, (kc + 2) * KTQ, m0, brow0);
        else
            cp_commit();

        uint32_t st = su + (kc % GSTG) * STAGE_SZ;
#pragma unroll
        for (int ks = 0; ks < 2; ks++) {       // 2 k32-slices per KT=64 chunk
            uint32_t ao = st + a_off + ks * 32;
            uint32_t bo = st + b_off + ks * 32;
            uint32_t a1f[4][4], a2f[4][4];
#pragma unroll
            for (int mb = 0; mb < 4; mb++) {
                ldsm_x4(a1f[mb], ao + mb * 16 * ROWB);
                ldsm_x4(a2f[mb], ao + (OFF_A2 - 0) + mb * 16 * ROWB);
            }
            uint32_t b1f[2][4], b2f[2][4];
#pragma unroll
            for (int g2_ = 0; g2_ < 2; g2_++) {
                ldsm_x4(b1f[g2_], bo + g2_ * 16 * ROWB);
                ldsm_x4(b2f[g2_], bo + (OFF_B2 - OFF_B1) + g2_ * 16 * ROWB);
            }
#pragma unroll
            for (int mb = 0; mb < 4; mb++)
#pragma unroll
                for (int nb = 0; nb < 4; nb++) {
                    const uint32_t* bf1 = &b1f[nb >> 1][(nb & 1) * 2];
                    const uint32_t* bf2 = &b2f[nb >> 1][(nb & 1) * 2];
                    mma_s8(hi[mb][nb], a1f[mb], bf1);
                    mma_s8(mi[mb][nb], a1f[mb], bf2);
                    mma_s8(mi[mb][nb], a2f[mb], bf1);
                }
        }
    }

    // epilogue: dequantize and store
    float* C = (proj == 0) ? c0 : (proj == 1) ? c1 : c2;
    int g = lane >> 2, q = lane & 3;
    int rb = (by & 31) * 128 + wm * 64;
    int rowA = by * 128 + wm * 64;
    int cb = bx * 64 + wn * 32;
#pragma unroll
    for (int mb = 0; mb < 4; mb++) {
        float sa0 = sa[rowA + mb * 16 + g];
        float sa1 = sa[rowA + mb * 16 + g + 8];
#pragma unroll
        for (int nt = 0; nt < 4; nt++) {
            int col = cb + nt * 8 + q * 2;
            float sb0 = sbv[proj * 1024 + col];
            float sb1 = sbv[proj * 1024 + col + 1];
            const int* h = hi[mb][nt];
            const int* m = mi[mb][nt];
            float f0 = sa0 * sb0 * ((float)h[0] + (float)m[0] * (1.f / 256.f));
            float f1 = sa0 * sb1 * ((float)h[1] + (float)m[1] * (1.f / 256.f));
            float f2 = sa1 * sb0 * ((float)h[2] + (float)m[2] * (1.f / 256.f));
            float f3 = sa1 * sb1 * ((float)h[3] + (float)m[3] * (1.f / 256.f));
            float* cp = C + (size_t)(rb + mb * 16 + g) * 1024 + col;
            *(float2*)cp = make_float2(f0, f1);
            *(float2*)(cp + 8 * 1024) = make_float2(f2, f3);
        }
    }
}

// ============================ sparse attention ============================
template<int AA>
__global__ void attn_kernel(const int* __restrict__ positions)
{
    int wid = (blockIdx.x * blockDim.x + threadIdx.x) >> 5;
    int lane = threadIdx.x & 31;
    if (wid >= B_ * H_ * T_) return;
    int t = wid % T_;
    int h = (wid / T_) % H_;
    int b = wid / (T_ * H_);

    const float* qp = g_q + ((size_t)b * T_ + t) * D_ + h * DH_;
    int d0 = lane * 2;
    float q0 = qp[d0], q1 = qp[d0 + 1];

    int nv = 1 + min(3, t);
    if (t >= 4) nv += (31 - __clz((unsigned)t)) - 1;

    float sc[AA];
    int ps[AA];
    float mx = -1e30f;
#pragma unroll
    for (int a = 0; a < AA; a++) {
        int pos = positions[t * AA + a];
        ps[a] = pos;
        const float* kp = g_k + ((size_t)b * T_ + pos) * D_ + h * DH_;
        float s = fmaf(q0, kp[d0], q1 * kp[d0 + 1]);
#pragma unroll
        for (int o = 16; o; o >>= 1) s += __shfl_xor_sync(0xffffffffu, s, o);
        s = (a < nv) ? s * 0.125f : -1e30f;
        sc[a] = s;
        mx = fmaxf(mx, s);
    }
    float sum = 0.f;
#pragma unroll
    for (int a = 0; a < AA; a++) { sc[a] = expf(sc[a] - mx); sum += sc[a]; }
    float inv = 1.f / sum;
    float o0 = 0.f, o1 = 0.f;
#pragma unroll
    for (int a = 0; a < AA; a++) {
        const float* vp = g_v + ((size_t)b * T_ + ps[a]) * D_ + h * DH_;
        float wgt = sc[a] * inv;
        o0 = fmaf(wgt, vp[d0], o0);
        o1 = fmaf(wgt, vp[d0 + 1], o1);
    }
    float* op = g_att + ((size_t)b * T_ + t) * D_ + h * DH_;
    *(float2*)(op + d0) = make_float2(o0, o1);
}

__global__ void attn_kernel_dyn(const int* __restrict__ positions, int A)
{
    int wid = (blockIdx.x * blockDim.x + threadIdx.x) >> 5;
    int lane = threadIdx.x & 31;
    if (wid >= B_ * H_ * T_) return;
    int t = wid % T_;
    int h = (wid / T_) % H_;
    int b = wid / (T_ * H_);
    const float* qp = g_q + ((size_t)b * T_ + t) * D_ + h * DH_;
    int d0 = lane * 2;
    float q0 = qp[d0], q1 = qp[d0 + 1];
    int nv = 1 + min(3, t);
    if (t >= 4) nv += (31 - __clz((unsigned)t)) - 1;
    float sc[32]; int ps[32];
    float mx = -1e30f;
    for (int a = 0; a < A; a++) {
        int pos = positions[t * A + a];
        ps[a] = pos;
        const float* kp = g_k + ((size_t)b * T_ + pos) * D_ + h * DH_;
        float s = fmaf(q0, kp[d0], q1 * kp[d0 + 1]);
        for (int o = 16; o; o >>= 1) s += __shfl_xor_sync(0xffffffffu, s, o);
        s = (a < nv) ? s * 0.125f : -1e30f;
        sc[a] = s; mx = fmaxf(mx, s);
    }
    float sum = 0.f;
    for (int a = 0; a < A; a++) { sc[a] = expf(sc[a] - mx); sum += sc[a]; }
    float inv = 1.f / sum;
    float o0 = 0.f, o1 = 0.f;
    for (int a = 0; a < A; a++) {
        const float* vp = g_v + ((size_t)b * T_ + ps[a]) * D_ + h * DH_;
        float wgt = sc[a] * inv;
        o0 = fmaf(wgt, vp[d0], o0);
        o1 = fmaf(wgt, vp[d0 + 1], o1);
    }
    float* op = g_att + ((size_t)b * T_ + t) * D_ + h * DH_;
    *(float2*)(op + d0) = make_float2(o0, o1);
}

// ============================ launcher ============================
extern "C" void kernel_launch(void* const* d_in, const int* in_sizes, int n_in,
                              void* d_out, int out_size)
{
    const float* x       = (const float*)d_in[0];
    const float* qkv_Wp  = (const float*)d_in[1];
    const float* qkv_Wi  = (const float*)d_in[2];
    const float* qkv_Wd  = (const float*)d_in[3];
    const float* gate_w  = (const float*)d_in[4];
    const float* gate_b  = (const float*)d_in[5];
    const float* kick_v  = (const float*)d_in[6];
    const float* kick_w  = (const float*)d_in[7];
    const float* kick_b  = (const float*)d_in[8];
    const float* o_w     = (const float*)d_in[9];
    const int*   positions = (const int*)d_in[10];
    int A = in_sizes[10] / T_;

    float* out = (float*)d_out;

    void *p_a1, *p_a2, *p_w1, *p_w2, *p_o1, *p_o2, *p_ow1, *p_ow2;
    void *p_sa, *p_sw, *p_so, *p_sow;
    void *p_q, *p_k, *p_v, *p_att;
    cudaGetSymbolAddress(&p_a1, g_a1);
    cudaGetSymbolAddress(&p_a2, g_a2);
    cudaGetSymbolAddress(&p_w1, g_w1);
    cudaGetSymbolAddress(&p_w2, g_w2);
    cudaGetSymbolAddress(&p_o1, g_o1);
    cudaGetSymbolAddress(&p_o2, g_o2);
    cudaGetSymbolAddress(&p_ow1, g_ow1);
    cudaGetSymbolAddress(&p_ow2, g_ow2);
    cudaGetSymbolAddress(&p_sa, g_sa);
    cudaGetSymbolAddress(&p_sw, g_sw);
    cudaGetSymbolAddress(&p_so, g_so);
    cudaGetSymbolAddress(&p_sow, g_sow);
    cudaGetSymbolAddress(&p_q, g_q);
    cudaGetSymbolAddress(&p_k, g_k);
    cudaGetSymbolAddress(&p_v, g_v);
    cudaGetSymbolAddress(&p_att, g_att);

    cudaFuncSetAttribute(gemm_s8, cudaFuncAttributeMaxDynamicSharedMemorySize, GEMM_SMEM);

    // 1. per-token gates / kick / stagnation
    token_stats_kernel<<<NTOK, 128>>>(x, gate_w, gate_b, kick_w, kick_b);
    // 2. EMA integral: 3-pass parallel chunked scan
    ema_pass1<<<(NCH * B_ * D_ + 255) / 256, 256>>>(x);
    ema_pass2<<<(B_ * D_ + 255) / 256, 256>>>();
    ema_pass3<<<((NCH - 1) * B_ * D_ + 255) / 256, 256>>>();
    // 3. quantize weights
    dim3 wg(1024, 3);
    conv_w_q<<<wg, 256>>>(qkv_Wp, qkv_Wi, qkv_Wd);
    quant_rows_q<<<1024, 256>>>(o_w, (int8_t*)p_ow1, (int8_t*)p_ow2, (float*)p_sow);
    // 4. build + quantize gated GEMM inputs
    dim3 gb(NTOK, 3);
    build_abc_q<<<gb, 256>>>(x, kick_v);
    // 5. projection GEMMs: grid (1024/64, 3*4096/128) = (16, 96)
    dim3 pgrid(16, 96);
    gemm_s8<<<pgrid, 128, GEMM_SMEM>>>(
        (const int8_t*)p_a1, (const int8_t*)p_a2,
        (const int8_t*)p_w1, (const int8_t*)p_w2,
        (const float*)p_sa, (const float*)p_sw,
        (float*)p_q, (float*)p_k, (float*)p_v, K3 / KTQ, K3);
    // 6. sparse dilated attention
    int nwarps = B_ * H_ * T_;
    int nblocks = nwarps / 4;
    if (A == 15)
        attn_kernel<15><<<nblocks, 128>>>(positions);
    else
        attn_kernel_dyn<<<nblocks, 128>>>(positions, A);
    // 7. quantize attention output, then output projection: grid (16, 32)
    quant_rows_q<<<NTOK, 256>>>((const float*)p_att, (int8_t*)p_o1, (int8_t*)p_o2, (float*)p_so);
    dim3 ogrid(16, 32);
    gemm_s8<<<ogrid, 128, GEMM_SMEM>>>(
        (const int8_t*)p_o1, (const int8_t*)p_o2,
        (const int8_t*)p_ow1, (const int8_t*)p_ow2,
        (const float*)p_so, (const float*)p_sow,
        out, out, out, D_ / KTQ, D_);
}